// round 10
// baseline (speedup 1.0000x reference)
#include <cuda_runtime.h>

#define RADIAL 160
#define RPB 2                        // rows per block
#define ROW_F 480                    // scalars per row
#define ROW_F4 120                   // float4 per row
#define NT 256                       // block size
#define NW 240                       // worker threads (output f4 per block)
#define LPAD 20                      // left zero pad (scalars), mult of 4
#define RPAD 20
#define SROWF 520                    // padded scalars per row
#define SROWF4 130

// Register component selector: scalar J (0..15) of window {V0..V3}.
template<int J>
__device__ __forceinline__ float getc(const float4 V0, const float4 V1,
                                      const float4 V2, const float4 V3) {
    if constexpr      (J == 0)  return V0.x;
    else if constexpr (J == 1)  return V0.y;
    else if constexpr (J == 2)  return V0.z;
    else if constexpr (J == 3)  return V0.w;
    else if constexpr (J == 4)  return V1.x;
    else if constexpr (J == 5)  return V1.y;
    else if constexpr (J == 6)  return V1.z;
    else if constexpr (J == 7)  return V1.w;
    else if constexpr (J == 8)  return V2.x;
    else if constexpr (J == 9)  return V2.y;
    else if constexpr (J == 10) return V2.z;
    else if constexpr (J == 11) return V2.w;
    else if constexpr (J == 12) return V3.x;
    else if constexpr (J == 13) return V3.y;
    else if constexpr (J == 14) return V3.z;
    else                        return V3.w;
}

// o_e = ce.x*W[P+e] + ce.y*W[P+e+3] + ce.z*W[P+e+6] + ce.w*W[P+e+9]
template<int P>
__device__ __forceinline__ float4 apply_taps(const float4 V0, const float4 V1,
                                             const float4 V2, const float4 V3,
                                             const float4 c0, const float4 c1,
                                             const float4 c2, const float4 c3) {
    float4 o;
    o.x = c0.x * getc<P + 0>(V0,V1,V2,V3) + c0.y * getc<P + 3>(V0,V1,V2,V3)
        + c0.z * getc<P + 6>(V0,V1,V2,V3) + c0.w * getc<P + 9>(V0,V1,V2,V3);
    o.y = c1.x * getc<P + 1>(V0,V1,V2,V3) + c1.y * getc<P + 4>(V0,V1,V2,V3)
        + c1.z * getc<P + 7>(V0,V1,V2,V3) + c1.w * getc<P + 10>(V0,V1,V2,V3);
    o.z = c2.x * getc<P + 2>(V0,V1,V2,V3) + c2.y * getc<P + 5>(V0,V1,V2,V3)
        + c2.z * getc<P + 8>(V0,V1,V2,V3) + c2.w * getc<P + 11>(V0,V1,V2,V3);
    o.w = c3.x * getc<P + 3>(V0,V1,V2,V3) + c3.y * getc<P + 6>(V0,V1,V2,V3)
        + c3.z * getc<P + 9>(V0,V1,V2,V3) + c3.w * getc<P + 12>(V0,V1,V2,V3);
    return o;
}

__global__ __launch_bounds__(NT, 6)
void beat_pulse_fused(const float* __restrict__ history,
                      const float* __restrict__ color_rgb,
                      const float* __restrict__ offset,
                      const float* __restrict__ persistence,
                      const float* __restrict__ diffusion01,
                      const float* __restrict__ dt_seconds,
                      const float* __restrict__ amount01,
                      const float* __restrict__ spread01,
                      float* __restrict__ out) {
    __shared__ float4 scoefv[RADIAL];    // per-bin fused taps (2.5 KB)
    __shared__ float  s1[RPB * SROWF];   // padded clipped history (4.1 KB)
    __shared__ int    sm_pG[2];          // alignment phase p, f4 shift G

    const int t = threadIdx.x;
    const long long base_row = (long long)blockIdx.x * RPB;
    const int row = (t < NW) ? (t / ROW_F4) : 0;
    const int r4  = (t < NW) ? (t - row * ROW_F4) : 0;

    // ---- issue the history load first (hide latency under coef compute) ----
    float4 v = make_float4(0.f, 0.f, 0.f, 0.f);
    if (t < NW)
        v = ((const float4*)(history + (base_row + row) * ROW_F))[r4];

    // ---- per-block param + coef computation (threads 0..159, one bin each) ----
    int myedge = 0;
    if (t < RADIAL) {
        float dt = fminf(fmaxf(*dt_seconds, 0.0f), 0.05f);
        float dts = dt * 60.0f;
        float off = (*offset) * dts;
        float P   = powf(*persistence, dts);
        float k   = 0.15f * (*diffusion01);
        float cc  = 1.0f - 2.0f * k;
        int   D   = (int)floorf(off);

        // edge check for bin t
        float npi = (float)t + off;
        bool validi = (npi >= 0.0f) && (npi < (float)(RADIAL - 1));
        int lii = min(max((int)floorf(npi), 0), RADIAL - 2);
        myedge = (validi && (lii != t + D)) ? 1 : 0;

        // fused advect+diffuse+fade coefficients for bin t
        const int bin = t;
        float fade = 1.0f;
        if (bin >= RADIAL - 8) {
            float tt = (float)(RADIAL - 1 - bin) * 0.125f;
            fade = tt * tt;
        }
        float c[4] = {0.0f, 0.0f, 0.0f, 0.0f};
        #pragma unroll
        for (int d = 0; d < 4; d++) {
            int src = bin - D - 2 + d;
            if (src < 0 || src >= RADIAL) continue;
            float nps = (float)src + off;            // same fp ops as reference
            if (!(nps >= 0.0f && nps < (float)(RADIAL - 1))) continue;
            int   ls  = min(max((int)floorf(nps), 0), RADIAL - 2);
            float fr  = nps - (float)ls;
            float wls = (1.0f - fr) * P;
            float wrs = fr * P;
            float sb  = (ls == bin     ? wls : 0.0f) + (ls + 1 == bin     ? wrs : 0.0f);
            float sbm = 0.0f, sbp = 0.0f;
            if (bin >= 1)
                sbm = (ls == bin - 1 ? wls : 0.0f) + (ls + 1 == bin - 1 ? wrs : 0.0f);
            if (bin <= RADIAL - 2)
                sbp = (ls == bin + 1 ? wls : 0.0f) + (ls + 1 == bin + 1 ? wrs : 0.0f);
            c[d] = (cc * sb + k * (sbm + sbp)) * fade;
        }
        scoefv[bin] = make_float4(c[0], c[1], c[2], c[3]);

        if (t == 0) {
            int b0 = LPAD - 3 * (D + 2);
            int p  = ((b0 % 4) + 4) % 4;
            sm_pG[0] = p;
            sm_pG[1] = (b0 - p) / 4;
        }
    }

    // ---- zero pads: 10 f4 per row ----
    if (t < RPB * 10) {
        int r = t / 10;
        int j = t - r * 10;
        int f4 = (j < 5) ? j : (SROWF4 - 5 + (j - 5));
        ((float4*)&s1[r * SROWF])[f4] = make_float4(0.f, 0.f, 0.f, 0.f);
    }

    // ---- inject + clip -> SMEM ----
    if (t < NW) {
        float vals[4] = {v.x, v.y, v.z, v.w};
        if (r4 < 4) {                         // inject region: scalars [0,15)
            float amount = fminf(fmaxf(*amount01, 0.0f), 1.0f);
            float spread = fminf(fmaxf(*spread01, 0.0f), 1.0f);
            float tight  = 1.0f - spread;
            float w[5] = {0.5f + 0.4f * tight, 0.2f * spread + 0.05f,
                          0.12f * spread, 0.06f * spread, 0.02f * spread};
            long long b = base_row + row;
            float en[3];
            en[0] = color_rgb[b * 3 + 0] * amount;
            en[1] = color_rgb[b * 3 + 1] * amount;
            en[2] = color_rgb[b * 3 + 2] * amount;
            #pragma unroll
            for (int e = 0; e < 4; e++) {
                int sidx = r4 * 4 + e;
                int bin  = sidx / 3;
                int ch   = sidx - bin * 3;
                if (bin < 5) vals[e] += en[ch] * w[bin];
            }
        }
        #pragma unroll
        for (int e = 0; e < 4; e++) vals[e] = fminf(fmaxf(vals[e], 0.0f), 1.0f);
        float4 o; o.x = vals[0]; o.y = vals[1]; o.z = vals[2]; o.w = vals[3];
        ((float4*)&s1[row * SROWF])[(LPAD / 4) + r4] = o;
    }

    // single barrier: publishes s1 + scoefv + sm_pG, reduces edge flag
    int edge = __syncthreads_or(myedge);

    if (!edge) {
        // ---- fast path: fused 4-tap banded operator, coalesced STG.128 ----
        if (t < NW) {
            int p = sm_pG[0];
            int G = sm_pG[1];
            int bf = min(max(r4 + G, 0), SROWF4 - 4);  // clamp => zero coefs there
            const float4* S4 = (const float4*)&s1[row * SROWF];
            float4 V0 = S4[bf + 0];
            float4 V1 = S4[bf + 1];
            float4 V2 = S4[bf + 2];
            float4 V3 = S4[bf + 3];

            int s0 = 4 * r4;
            int bA = s0 / 3;                           // 0..158
            float4 cA = scoefv[bA];
            float4 cB = scoefv[min(bA + 1, RADIAL - 1)];
            int L = 3 * bA + 3 - s0;                   // scalars e < L are bin bA
            float4 c0 = cA;                            // L >= 1 always
            float4 c1 = (1 < L) ? cA : cB;
            float4 c2 = (2 < L) ? cA : cB;
            float4 c3 = (3 < L) ? cA : cB;

            float4 o;
            switch (p) {                               // uniform branch
                case 0:  o = apply_taps<0>(V0,V1,V2,V3,c0,c1,c2,c3); break;
                case 1:  o = apply_taps<1>(V0,V1,V2,V3,c0,c1,c2,c3); break;
                case 2:  o = apply_taps<2>(V0,V1,V2,V3,c0,c1,c2,c3); break;
                default: o = apply_taps<3>(V0,V1,V2,V3,c0,c1,c2,c3); break;
            }
            ((float4*)out)[(base_row + row) * ROW_F4 + r4] = o;
        }
    } else {
        // ---- generic fallback (block-uniform; never taken for bench params) ----
        float dt = fminf(fmaxf(*dt_seconds, 0.0f), 0.05f);
        float dts = dt * 60.0f;
        float off = (*offset) * dts;
        float P   = powf(*persistence, dts);
        float k   = 0.15f * (*diffusion01);
        float cc  = 1.0f - 2.0f * k;
        int   D   = (int)floorf(off);

        float adv[2][3];
        int nloc = 0;
        for (int bb = t; bb < RPB * RADIAL; bb += NT, nloc++) {
            int rr  = bb / RADIAL;
            int bin = bb - rr * RADIAL;
            const float* s1r = s1 + rr * SROWF + LPAD;
            float wk0 = 0.0f, wk1 = 0.0f, wk2 = 0.0f;
            #pragma unroll
            for (int d = -2; d <= 1; d++) {
                int i = bin - D + d;
                float np = (float)i + off;
                float lf = floorf(np);
                int   li = (int)lf;
                float fr = np - lf;
                bool vs = (i >= 0) & (i < RADIAL) &
                          (np >= 0.0f) & (np < (float)(RADIAL - 1));
                float wl = (vs && li == bin)     ? (1.0f - fr) * P : 0.0f;
                float wr = (vs && li == bin - 1) ? fr * P          : 0.0f;
                float w = wl + wr;
                int a = min(max(i, 0), RADIAL - 1) * 3;
                wk0 += w * s1r[a + 0];
                wk1 += w * s1r[a + 1];
                wk2 += w * s1r[a + 2];
            }
            adv[nloc][0] = wk0; adv[nloc][1] = wk1; adv[nloc][2] = wk2;
        }
        __syncthreads();
        nloc = 0;
        for (int bb = t; bb < RPB * RADIAL; bb += NT, nloc++) {
            int rr  = bb / RADIAL;
            int bin = bb - rr * RADIAL;
            float* s1r = s1 + rr * SROWF + LPAD;
            s1r[bin * 3 + 0] = adv[nloc][0];
            s1r[bin * 3 + 1] = adv[nloc][1];
            s1r[bin * 3 + 2] = adv[nloc][2];
        }
        __syncthreads();
        for (int bb = t; bb < RPB * RADIAL; bb += NT) {
            int rr  = bb / RADIAL;
            int bin = bb - rr * RADIAL;
            const float* s1r = s1 + rr * SROWF + LPAD;
            float fade = 1.0f;
            if (bin >= RADIAL - 8) {
                float tt = (float)(RADIAL - 1 - bin) * 0.125f;
                fade = tt * tt;
            }
            float* gout = out + (base_row + rr) * ROW_F + bin * 3;
            #pragma unroll
            for (int c = 0; c < 3; c++) {
                float xc = s1r[bin * 3 + c];
                float xm = s1r[(bin - 1) * 3 + c];   // pads give zero boundary
                float xp = s1r[(bin + 1) * 3 + c];
                gout[c] = (cc * xc + k * xm + k * xp) * fade;
            }
        }
    }
}

extern "C" void kernel_launch(void* const* d_in, const int* in_sizes, int n_in,
                              void* d_out, int out_size) {
    const float* history     = (const float*)d_in[0];
    const float* color_rgb   = (const float*)d_in[1];
    const float* offset      = (const float*)d_in[2];
    const float* persistence = (const float*)d_in[3];
    const float* diffusion01 = (const float*)d_in[4];
    const float* dt_seconds  = (const float*)d_in[5];
    const float* amount01    = (const float*)d_in[6];
    const float* spread01    = (const float*)d_in[7];
    float* out = (float*)d_out;

    int nrows = in_sizes[0] / ROW_F;                 // 65536
    int grid  = (nrows + RPB - 1) / RPB;             // 32768

    beat_pulse_fused<<<grid, NT>>>(history, color_rgb, offset, persistence,
                                   diffusion01, dt_seconds, amount01, spread01,
                                   out);
}

// round 11
// speedup vs baseline: 1.3292x; 1.3292x over previous
#include <cuda_runtime.h>

#define RADIAL 160
#define RPB 2                        // rows per block
#define ROW_F 480                    // scalars per row
#define ROW_F4 120                   // float4 per row
#define NT 256                       // block size
#define NW 240                       // worker threads (output f4 per block)
#define LPAD 20                      // left zero pad (scalars), mult of 4
#define RPAD 20
#define SROWF 520                    // padded scalars per row
#define SROWF4 130

struct Params {
    float dt_offset;
    float dt_persist;
    float k, cc;
    float amount;
    float w[5];
    int   D;
    int   edge;
    int   p;        // uniform alignment phase 0..3
    int   G;        // uniform f4 window shift: bf = r4 + G
};

__device__ Params g_params;
__device__ float4 g_coef[RADIAL];    // fused advect+diffuse+fade taps per bin

__global__ void prep_kernel(const float* __restrict__ offset,
                            const float* __restrict__ persistence,
                            const float* __restrict__ diffusion01,
                            const float* __restrict__ dt_seconds,
                            const float* __restrict__ amount01,
                            const float* __restrict__ spread01) {
    const int bin = threadIdx.x;     // 160 threads, one per bin

    float dt = fminf(fmaxf(*dt_seconds, 0.0f), 0.05f);
    float dts = dt * 60.0f;
    float off = (*offset) * dts;
    float P   = powf(*persistence, dts);
    float k   = 0.15f * (*diffusion01);
    float cc  = 1.0f - 2.0f * k;
    int   D   = (int)floorf(off);

    // Edge check: does floor(bin + off) deviate from bin + D for any valid bin?
    float npi = (float)bin + off;
    bool validi = (npi >= 0.0f) && (npi < (float)(RADIAL - 1));
    int lii = min(max((int)floorf(npi), 0), RADIAL - 2);
    int myedge = (validi && (lii != bin + D)) ? 1 : 0;
    int edge = __syncthreads_or(myedge);

    if (bin == 0) {
        g_params.dt_offset  = off;
        g_params.dt_persist = P;
        g_params.k  = k;
        g_params.cc = cc;
        g_params.D  = D;
        g_params.edge = edge;
        g_params.amount = fminf(fmaxf(*amount01, 0.0f), 1.0f);
        float spread = fminf(fmaxf(*spread01, 0.0f), 1.0f);
        float tight  = 1.0f - spread;
        g_params.w[0] = 0.5f + 0.4f * tight;
        g_params.w[1] = 0.2f * spread + 0.05f;
        g_params.w[2] = 0.12f * spread;
        g_params.w[3] = 0.06f * spread;
        g_params.w[4] = 0.02f * spread;
        int b0 = LPAD - 3 * (D + 2);
        int p  = ((b0 % 4) + 4) % 4;
        g_params.p = p;
        g_params.G = (b0 - p) / 4;
    }

    // Fused per-bin coefficients: out[bin] = sum_d c[d] * hclip[bin-D-2+d]
    float fade = 1.0f;
    if (bin >= RADIAL - 8) {
        float tt = (float)(RADIAL - 1 - bin) * 0.125f;
        fade = tt * tt;
    }
    float c[4] = {0.0f, 0.0f, 0.0f, 0.0f};
    #pragma unroll
    for (int d = 0; d < 4; d++) {
        int src = bin - D - 2 + d;
        if (src < 0 || src >= RADIAL) continue;
        float nps = (float)src + off;               // same fp ops as reference
        if (!(nps >= 0.0f && nps < (float)(RADIAL - 1))) continue;
        int   ls  = min(max((int)floorf(nps), 0), RADIAL - 2);
        float fr  = nps - (float)ls;
        float wls = (1.0f - fr) * P;
        float wrs = fr * P;
        float sb  = (ls == bin     ? wls : 0.0f) + (ls + 1 == bin     ? wrs : 0.0f);
        float sbm = 0.0f, sbp = 0.0f;
        if (bin >= 1)
            sbm = (ls == bin - 1 ? wls : 0.0f) + (ls + 1 == bin - 1 ? wrs : 0.0f);
        if (bin <= RADIAL - 2)
            sbp = (ls == bin + 1 ? wls : 0.0f) + (ls + 1 == bin + 1 ? wrs : 0.0f);
        c[d] = (cc * sb + k * (sbm + sbp)) * fade;
    }
    g_coef[bin] = make_float4(c[0], c[1], c[2], c[3]);
}

// Register component selector: scalar J (0..15) of window {V0..V3}.
template<int J>
__device__ __forceinline__ float getc(const float4 V0, const float4 V1,
                                      const float4 V2, const float4 V3) {
    if constexpr      (J == 0)  return V0.x;
    else if constexpr (J == 1)  return V0.y;
    else if constexpr (J == 2)  return V0.z;
    else if constexpr (J == 3)  return V0.w;
    else if constexpr (J == 4)  return V1.x;
    else if constexpr (J == 5)  return V1.y;
    else if constexpr (J == 6)  return V1.z;
    else if constexpr (J == 7)  return V1.w;
    else if constexpr (J == 8)  return V2.x;
    else if constexpr (J == 9)  return V2.y;
    else if constexpr (J == 10) return V2.z;
    else if constexpr (J == 11) return V2.w;
    else if constexpr (J == 12) return V3.x;
    else if constexpr (J == 13) return V3.y;
    else if constexpr (J == 14) return V3.z;
    else                        return V3.w;
}

// o_e = ce.x*W[P+e] + ce.y*W[P+e+3] + ce.z*W[P+e+6] + ce.w*W[P+e+9]
template<int P>
__device__ __forceinline__ float4 apply_taps(const float4 V0, const float4 V1,
                                             const float4 V2, const float4 V3,
                                             const float4 c0, const float4 c1,
                                             const float4 c2, const float4 c3) {
    float4 o;
    o.x = c0.x * getc<P + 0>(V0,V1,V2,V3) + c0.y * getc<P + 3>(V0,V1,V2,V3)
        + c0.z * getc<P + 6>(V0,V1,V2,V3) + c0.w * getc<P + 9>(V0,V1,V2,V3);
    o.y = c1.x * getc<P + 1>(V0,V1,V2,V3) + c1.y * getc<P + 4>(V0,V1,V2,V3)
        + c1.z * getc<P + 7>(V0,V1,V2,V3) + c1.w * getc<P + 10>(V0,V1,V2,V3);
    o.z = c2.x * getc<P + 2>(V0,V1,V2,V3) + c2.y * getc<P + 5>(V0,V1,V2,V3)
        + c2.z * getc<P + 8>(V0,V1,V2,V3) + c2.w * getc<P + 11>(V0,V1,V2,V3);
    o.w = c3.x * getc<P + 3>(V0,V1,V2,V3) + c3.y * getc<P + 6>(V0,V1,V2,V3)
        + c3.z * getc<P + 9>(V0,V1,V2,V3) + c3.w * getc<P + 12>(V0,V1,V2,V3);
    return o;
}

__global__ __launch_bounds__(NT, 7)
void beat_pulse_kernel(const float* __restrict__ history,
                       const float* __restrict__ color_rgb,
                       float* __restrict__ out) {
    __shared__ float s1[RPB * SROWF];    // padded clipped history (4.1 KB)

    const int t = threadIdx.x;
    const long long base_row = (long long)blockIdx.x * RPB;
    const int row = (t < NW) ? (t / ROW_F4) : 0;
    const int r4  = (t < NW) ? (t - row * ROW_F4) : 0;

    // ---- zero pads: 10 f4 per row ----
    if (t >= NW) {
        int j = t - NW;                   // 0..15 covers 16 of 20 pad f4
        if (j < 16) {
            int r = j / 8;
            int q = j - r * 8;
            int f4 = (q < 4) ? q : (SROWF4 - 5 + (q - 4));
            ((float4*)&s1[r * SROWF])[f4] = make_float4(0.f, 0.f, 0.f, 0.f);
        }
    } else if (t < RPB * 2) {             // remaining 4 pad f4 (index 4 & 126)
        int r = t / 2;
        int f4 = (t & 1) ? 4 : (SROWF4 - 1);
        ((float4*)&s1[r * SROWF])[f4] = make_float4(0.f, 0.f, 0.f, 0.f);
    }

    // ---- Phase 1: coalesced float4 load + inject + clip01 -> SMEM ----
    if (t < NW) {
        const float* gin = history + (base_row + row) * ROW_F;
        float4 v = ((const float4*)gin)[r4];
        float vals[4] = {v.x, v.y, v.z, v.w};
        if (r4 < 4) {                     // inject region: scalars [0,15)
            long long b = base_row + row;
            float amount = g_params.amount;
            float en[3];
            en[0] = color_rgb[b * 3 + 0] * amount;
            en[1] = color_rgb[b * 3 + 1] * amount;
            en[2] = color_rgb[b * 3 + 2] * amount;
            #pragma unroll
            for (int e = 0; e < 4; e++) {
                int sidx = r4 * 4 + e;
                int bin  = sidx / 3;
                int ch   = sidx - bin * 3;
                if (bin < 5) vals[e] += en[ch] * g_params.w[bin];
            }
        }
        #pragma unroll
        for (int e = 0; e < 4; e++) vals[e] = fminf(fmaxf(vals[e], 0.0f), 1.0f);
        float4 o; o.x = vals[0]; o.y = vals[1]; o.z = vals[2]; o.w = vals[3];
        ((float4*)&s1[row * SROWF])[(LPAD / 4) + r4] = o;
    }
    __syncthreads();

    if (!g_params.edge) {
        // ---- fast path: fused 4-tap banded operator, coalesced STG.128 ----
        if (t < NW) {
            int bf = min(max(r4 + g_params.G, 0), SROWF4 - 4); // clamp => zero coefs
            const float4* S4 = (const float4*)&s1[row * SROWF];
            float4 V0 = S4[bf + 0];
            float4 V1 = S4[bf + 1];
            float4 V2 = S4[bf + 2];
            float4 V3 = S4[bf + 3];

            int s0 = 4 * r4;
            int bA = s0 / 3;                                   // 0..158
            float4 cA = __ldg(&g_coef[bA]);
            float4 cB = __ldg(&g_coef[min(bA + 1, RADIAL - 1)]);
            int L = 3 * bA + 3 - s0;          // scalars e < L belong to bin bA
            float4 c0 = cA;                   // L >= 1 always
            float4 c1 = (1 < L) ? cA : cB;
            float4 c2 = (2 < L) ? cA : cB;
            float4 c3 = (3 < L) ? cA : cB;

            float4 o;
            switch (g_params.p) {             // uniform branch
                case 0:  o = apply_taps<0>(V0,V1,V2,V3,c0,c1,c2,c3); break;
                case 1:  o = apply_taps<1>(V0,V1,V2,V3,c0,c1,c2,c3); break;
                case 2:  o = apply_taps<2>(V0,V1,V2,V3,c0,c1,c2,c3); break;
                default: o = apply_taps<3>(V0,V1,V2,V3,c0,c1,c2,c3); break;
            }
            ((float4*)out)[(base_row + row) * ROW_F4 + r4] = o;
        }
    } else {
        // ---- generic fallback (never taken for bench params) ----
        const float off = g_params.dt_offset;
        const float P   = g_params.dt_persist;
        const float k   = g_params.k;
        const float cc  = g_params.cc;
        const int   D   = g_params.D;

        float adv[2][3];
        int nloc = 0;
        for (int bb = t; bb < RPB * RADIAL; bb += NT, nloc++) {
            int rr  = bb / RADIAL;
            int bin = bb - rr * RADIAL;
            const float* s1r = s1 + rr * SROWF + LPAD;
            float wk0 = 0.0f, wk1 = 0.0f, wk2 = 0.0f;
            #pragma unroll
            for (int d = -2; d <= 1; d++) {
                int i = bin - D + d;
                float np = (float)i + off;
                float lf = floorf(np);
                int   li = (int)lf;
                float fr = np - lf;
                bool vs = (i >= 0) & (i < RADIAL) &
                          (np >= 0.0f) & (np < (float)(RADIAL - 1));
                float wl = (vs && li == bin)     ? (1.0f - fr) * P : 0.0f;
                float wr = (vs && li == bin - 1) ? fr * P          : 0.0f;
                float w = wl + wr;
                int a = min(max(i, 0), RADIAL - 1) * 3;
                wk0 += w * s1r[a + 0];
                wk1 += w * s1r[a + 1];
                wk2 += w * s1r[a + 2];
            }
            adv[nloc][0] = wk0; adv[nloc][1] = wk1; adv[nloc][2] = wk2;
        }
        __syncthreads();
        nloc = 0;
        for (int bb = t; bb < RPB * RADIAL; bb += NT, nloc++) {
            int rr  = bb / RADIAL;
            int bin = bb - rr * RADIAL;
            float* s1r = s1 + rr * SROWF + LPAD;
            s1r[bin * 3 + 0] = adv[nloc][0];
            s1r[bin * 3 + 1] = adv[nloc][1];
            s1r[bin * 3 + 2] = adv[nloc][2];
        }
        __syncthreads();
        for (int bb = t; bb < RPB * RADIAL; bb += NT) {
            int rr  = bb / RADIAL;
            int bin = bb - rr * RADIAL;
            const float* s1r = s1 + rr * SROWF + LPAD;
            float fade = 1.0f;
            if (bin >= RADIAL - 8) {
                float tt = (float)(RADIAL - 1 - bin) * 0.125f;
                fade = tt * tt;
            }
            float* gout = out + (base_row + rr) * ROW_F + bin * 3;
            #pragma unroll
            for (int c = 0; c < 3; c++) {
                float xc = s1r[bin * 3 + c];
                float xm = s1r[(bin - 1) * 3 + c];   // pads give zero boundary
                float xp = s1r[(bin + 1) * 3 + c];
                gout[c] = (cc * xc + k * xm + k * xp) * fade;
            }
        }
    }
}

extern "C" void kernel_launch(void* const* d_in, const int* in_sizes, int n_in,
                              void* d_out, int out_size) {
    const float* history     = (const float*)d_in[0];
    const float* color_rgb   = (const float*)d_in[1];
    const float* offset      = (const float*)d_in[2];
    const float* persistence = (const float*)d_in[3];
    const float* diffusion01 = (const float*)d_in[4];
    const float* dt_seconds  = (const float*)d_in[5];
    const float* amount01    = (const float*)d_in[6];
    const float* spread01    = (const float*)d_in[7];
    float* out = (float*)d_out;

    int nrows = in_sizes[0] / ROW_F;                 // 65536
    int grid  = (nrows + RPB - 1) / RPB;             // 32768

    prep_kernel<<<1, RADIAL>>>(offset, persistence, diffusion01, dt_seconds,
                               amount01, spread01);
    beat_pulse_kernel<<<grid, NT>>>(history, color_rgb, out);
}

// round 12
// speedup vs baseline: 1.7846x; 1.3426x over previous
#include <cuda_runtime.h>
#include <cstdint>

#define RADIAL 160
#define RPB 8                         // rows per block (65536 % 8 == 0)
#define ROW_F 480                     // scalars per row
#define F4R 120                       // float4 per row
#define NT 320                        // block size = RPB*40, all compute
#define TOT (RPB * F4R)               // 960 f4
#define GUARD 12                      // zeroed guard f4 each side of sIn
#define SINF4 (TOT + 2 * GUARD)       // 984

struct Params {
    float dt_offset, dt_persist, k, cc, amount;
    float w[5];
    int   D, edge;
    int   p;        // alignment phase 0..3
    int   G2;       // row-local f4 window shift: wq = q + G2
};

__device__ Params g_params;
__device__ float4 g_coefP[RADIAL];    // plane layout: [(bin&3)*40 + (bin>>2)]

__global__ void prep_kernel(const float* __restrict__ offset,
                            const float* __restrict__ persistence,
                            const float* __restrict__ diffusion01,
                            const float* __restrict__ dt_seconds,
                            const float* __restrict__ amount01,
                            const float* __restrict__ spread01) {
    const int bin = threadIdx.x;      // 160 threads

    float dt = fminf(fmaxf(*dt_seconds, 0.0f), 0.05f);
    float dts = dt * 60.0f;
    float off = (*offset) * dts;
    float P   = powf(*persistence, dts);
    float k   = 0.15f * (*diffusion01);
    float cc  = 1.0f - 2.0f * k;
    int   D   = (int)floorf(off);

    float npi = (float)bin + off;
    bool validi = (npi >= 0.0f) && (npi < (float)(RADIAL - 1));
    int lii = min(max((int)floorf(npi), 0), RADIAL - 2);
    int myedge = (validi && (lii != bin + D)) ? 1 : 0;
    int edge = __syncthreads_or(myedge);

    if (bin == 0) {
        g_params.dt_offset  = off;
        g_params.dt_persist = P;
        g_params.k  = k;  g_params.cc = cc;
        g_params.D  = D;  g_params.edge = edge;
        g_params.amount = fminf(fmaxf(*amount01, 0.0f), 1.0f);
        float spread = fminf(fmaxf(*spread01, 0.0f), 1.0f);
        float tight  = 1.0f - spread;
        g_params.w[0] = 0.5f + 0.4f * tight;
        g_params.w[1] = 0.2f * spread + 0.05f;
        g_params.w[2] = 0.12f * spread;
        g_params.w[3] = 0.06f * spread;
        g_params.w[4] = 0.02f * spread;
        int b0 = -3 * (D + 2);                   // row-local tap base
        int p  = ((b0 % 4) + 4) % 4;
        g_params.p  = p;
        g_params.G2 = (b0 - p) / 4;
    }

    // Fused per-bin coefficients: out[bin] = sum_d c[d] * hclip[bin-D-2+d]
    float fade = 1.0f;
    if (bin >= RADIAL - 8) {
        float tt = (float)(RADIAL - 1 - bin) * 0.125f;
        fade = tt * tt;
    }
    float c[4] = {0.0f, 0.0f, 0.0f, 0.0f};
    #pragma unroll
    for (int d = 0; d < 4; d++) {
        int src = bin - D - 2 + d;
        if (src < 0 || src >= RADIAL) continue;
        float nps = (float)src + off;            // same fp ops as reference
        if (!(nps >= 0.0f && nps < (float)(RADIAL - 1))) continue;
        int   ls  = min(max((int)floorf(nps), 0), RADIAL - 2);
        float fr  = nps - (float)ls;
        float wls = (1.0f - fr) * P;
        float wrs = fr * P;
        float sb  = (ls == bin     ? wls : 0.0f) + (ls + 1 == bin     ? wrs : 0.0f);
        float sbm = 0.0f, sbp = 0.0f;
        if (bin >= 1)
            sbm = (ls == bin - 1 ? wls : 0.0f) + (ls + 1 == bin - 1 ? wrs : 0.0f);
        if (bin <= RADIAL - 2)
            sbp = (ls == bin + 1 ? wls : 0.0f) + (ls + 1 == bin + 1 ? wrs : 0.0f);
        c[d] = (cc * sb + k * (sbm + sbp)) * fade;
    }
    g_coefP[(bin & 3) * 40 + (bin >> 2)] = make_float4(c[0], c[1], c[2], c[3]);
}

// ---- PTX helpers ----
__device__ __forceinline__ uint32_t smem_u32(const void* p) {
    uint32_t a;
    asm("{ .reg .u64 t; cvta.to.shared.u64 t, %1; cvt.u32.u64 %0, t; }"
        : "=r"(a) : "l"(p));
    return a;
}

// scalar J (0..23) of window {w0..w5}
template<int J>
__device__ __forceinline__ float gw(const float4 w0, const float4 w1,
                                    const float4 w2, const float4 w3,
                                    const float4 w4, const float4 w5) {
    constexpr int F = J / 4, C = J % 4;
    const float4 v = (F == 0) ? w0 : (F == 1) ? w1 : (F == 2) ? w2
                   : (F == 3) ? w3 : (F == 4) ? w4 : w5;
    if constexpr      (C == 0) return v.x;
    else if constexpr (C == 1) return v.y;
    else if constexpr (C == 2) return v.z;
    else                       return v.w;
}

#define GW(J) gw<(P) + (J)>(w0, w1, w2, w3, w4, w5)
#define TAPE(e, cf) ((cf).x * GW(e) + (cf).y * GW((e) + 3) + \
                     (cf).z * GW((e) + 6) + (cf).w * GW((e) + 9))

template<int P>
__device__ __forceinline__ void apply12(const float4 w0, const float4 w1,
                                        const float4 w2, const float4 w3,
                                        const float4 w4, const float4 w5,
                                        const float4 c0, const float4 c1,
                                        const float4 c2, const float4 c3,
                                        float4& o0, float4& o1, float4& o2) {
    o0.x = TAPE(0, c0);  o0.y = TAPE(1, c0);  o0.z = TAPE(2, c0);  o0.w = TAPE(3, c1);
    o1.x = TAPE(4, c1);  o1.y = TAPE(5, c1);  o1.z = TAPE(6, c2);  o1.w = TAPE(7, c2);
    o2.x = TAPE(8, c2);  o2.y = TAPE(9, c3);  o2.z = TAPE(10, c3); o2.w = TAPE(11, c3);
}

__device__ __forceinline__ float4 clamp01_4(float4 v) {
    v.x = fminf(fmaxf(v.x, 0.0f), 1.0f);
    v.y = fminf(fmaxf(v.y, 0.0f), 1.0f);
    v.z = fminf(fmaxf(v.z, 0.0f), 1.0f);
    v.w = fminf(fmaxf(v.w, 0.0f), 1.0f);
    return v;
}

// generic-path helper: inject + clip one (row, srcbin, ch) from global
__device__ __forceinline__ float loadclip(const float* __restrict__ history,
                                          const float* __restrict__ color_rgb,
                                          long long row, int srcbin, int ch) {
    int sb = min(max(srcbin, 0), RADIAL - 1);
    float v = history[row * ROW_F + sb * 3 + ch];
    if (sb < 5)
        v += color_rgb[row * 3 + ch] * g_params.amount * g_params.w[sb];
    return fminf(fmaxf(v, 0.0f), 1.0f);
}

__global__ __launch_bounds__(NT)
void beat_pulse_tma(const float* __restrict__ history,
                    const float* __restrict__ color_rgb,
                    float* __restrict__ out) {
    __shared__ float4 sIn[SINF4];                 // raw rows + zero guards
    __shared__ float4 sOut[TOT];                  // results
    __shared__ float4 sCoef[RADIAL];              // plane-layout coefs
    __shared__ alignas(8) unsigned long long mbar;

    const int t = threadIdx.x;
    const long long base_row = (long long)blockIdx.x * RPB;
    const uint32_t mbar_a = smem_u32(&mbar);

    if (t == 0)
        asm volatile("mbarrier.init.shared.b64 [%0], 1;" :: "r"(mbar_a) : "memory");
    __syncthreads();                              // publish mbar init

    if (t == 0) {
        const uint32_t dst = smem_u32(sIn) + GUARD * 16;
        const float* src = history + base_row * ROW_F;
        asm volatile("mbarrier.arrive.expect_tx.shared.b64 _, [%0], %1;"
                     :: "r"(mbar_a), "r"((uint32_t)(TOT * 16)) : "memory");
        asm volatile(
            "cp.async.bulk.shared::cluster.global.mbarrier::complete_tx::bytes "
            "[%0], [%1], %2, [%3];"
            :: "r"(dst), "l"(src), "r"((uint32_t)(TOT * 16)), "r"(mbar_a)
            : "memory");
    }

    // zero guards (independent of TMA data)
    if (t < 2 * GUARD) {
        int idx = (t < GUARD) ? t : (GUARD + TOT + (t - GUARD));
        sIn[idx] = make_float4(0.f, 0.f, 0.f, 0.f);
    }
    // stage coef planes
    if (t < RADIAL) sCoef[t] = __ldg(&g_coefP[t]);

    // wait for TMA (acquire)
    {
        uint32_t done;
        asm volatile(
            "{\n\t.reg .pred p;\n\t"
            "mbarrier.try_wait.parity.acquire.cta.shared::cta.b64 p, [%1], 0;\n\t"
            "selp.b32 %0, 1, 0, p;\n\t}"
            : "=r"(done) : "r"(mbar_a) : "memory");
        if (!done) {
            asm volatile(
                "{\n\t.reg .pred P1;\n\t"
                "WL_%=:\n\t"
                "mbarrier.try_wait.parity.acquire.cta.shared::cta.b64 P1, [%0], 0, 0x989680;\n\t"
                "@P1 bra.uni WD_%=;\n\t"
                "bra.uni WL_%=;\n\t"
                "WD_%=:\n\t}"
                :: "r"(mbar_a) : "memory");
        }
    }

    // inject (raw add; clip happens at window read) — 4 f4 per row
    if (t >= 64 && t < 64 + RPB * 4) {
        int idx = t - 64;
        int row = idx >> 2;
        int j   = idx & 3;
        float4 v = sIn[GUARD + row * F4R + j];
        float vals[4] = {v.x, v.y, v.z, v.w};
        long long b = base_row + row;
        float amount = g_params.amount;
        float en[3];
        en[0] = color_rgb[b * 3 + 0] * amount;
        en[1] = color_rgb[b * 3 + 1] * amount;
        en[2] = color_rgb[b * 3 + 2] * amount;
        #pragma unroll
        for (int e = 0; e < 4; e++) {
            int sidx = j * 4 + e;
            int bin  = sidx / 3;
            int ch   = sidx - bin * 3;
            if (bin < 5) vals[e] += en[ch] * g_params.w[bin];
        }
        sIn[GUARD + row * F4R + j] = make_float4(vals[0], vals[1], vals[2], vals[3]);
    }
    __syncthreads();

    if (!g_params.edge) {
        // ---- fast path: 12 scalars (4 bins) per thread ----
        const int row = t / 40;
        const int u40 = t - row * 40;
        const int q   = 3 * u40;

        int wb = GUARD + row * F4R + q + g_params.G2;
        wb = min(max(wb, 0), SINF4 - 6);
        float4 w0 = clamp01_4(sIn[wb + 0]);
        float4 w1 = clamp01_4(sIn[wb + 1]);
        float4 w2 = clamp01_4(sIn[wb + 2]);
        float4 w3 = clamp01_4(sIn[wb + 3]);
        float4 w4 = clamp01_4(sIn[wb + 4]);
        float4 w5 = clamp01_4(sIn[wb + 5]);

        float4 c0 = sCoef[0 * 40 + u40];
        float4 c1 = sCoef[1 * 40 + u40];
        float4 c2 = sCoef[2 * 40 + u40];
        float4 c3 = sCoef[3 * 40 + u40];

        float4 o0, o1, o2;
        switch (g_params.p) {                     // uniform branch
            case 0:  apply12<0>(w0,w1,w2,w3,w4,w5,c0,c1,c2,c3,o0,o1,o2); break;
            case 1:  apply12<1>(w0,w1,w2,w3,w4,w5,c0,c1,c2,c3,o0,o1,o2); break;
            case 2:  apply12<2>(w0,w1,w2,w3,w4,w5,c0,c1,c2,c3,o0,o1,o2); break;
            default: apply12<3>(w0,w1,w2,w3,w4,w5,c0,c1,c2,c3,o0,o1,o2); break;
        }
        sOut[row * F4R + q + 0] = o0;
        sOut[row * F4R + q + 1] = o1;
        sOut[row * F4R + q + 2] = o2;

        asm volatile("fence.proxy.async.shared::cta;" ::: "memory");
        __syncthreads();

        if (t == 0) {
            const uint32_t src = smem_u32(sOut);
            float* dst = out + base_row * ROW_F;
            asm volatile("cp.async.bulk.global.shared::cta.bulk_group [%0], [%1], %2;"
                         :: "l"(dst), "r"(src), "r"((uint32_t)(TOT * 16)) : "memory");
            asm volatile("cp.async.bulk.commit_group;" ::: "memory");
            asm volatile("cp.async.bulk.wait_group 0;" ::: "memory");
        }
    } else {
        // ---- generic fallback from global (never taken for bench params) ----
        const float off = g_params.dt_offset;
        const float P   = g_params.dt_persist;
        const float k   = g_params.k;
        const float cc  = g_params.cc;
        const int   D   = g_params.D;
        const int row = t / 40;
        const int u40 = t - row * 40;
        const long long grow = base_row + row;

        #pragma unroll
        for (int e = 0; e < 12; e++) {
            int s   = 12 * u40 + e;
            int bin = s / 3;
            int ch  = s - 3 * bin;
            float adv[3];
            #pragma unroll
            for (int bo = -1; bo <= 1; bo++) {
                int bb = bin + bo;
                float a = 0.0f;
                if (bb >= 0 && bb < RADIAL) {
                    #pragma unroll
                    for (int d = -2; d <= 1; d++) {
                        int i = bb - D + d;
                        float np = (float)i + off;
                        float lf = floorf(np);
                        int   li = (int)lf;
                        float fr = np - lf;
                        bool vs = (i >= 0) & (i < RADIAL) &
                                  (np >= 0.0f) & (np < (float)(RADIAL - 1));
                        float wl = (vs && li == bb)     ? (1.0f - fr) * P : 0.0f;
                        float wr = (vs && li == bb - 1) ? fr * P          : 0.0f;
                        float w = wl + wr;
                        if (w != 0.0f)
                            a += w * loadclip(history, color_rgb, grow, i, ch);
                    }
                }
                adv[bo + 1] = a;
            }
            float fade = 1.0f;
            if (bin >= RADIAL - 8) {
                float tt = (float)(RADIAL - 1 - bin) * 0.125f;
                fade = tt * tt;
            }
            out[grow * ROW_F + s] = (cc * adv[1] + k * adv[0] + k * adv[2]) * fade;
        }
    }
}

extern "C" void kernel_launch(void* const* d_in, const int* in_sizes, int n_in,
                              void* d_out, int out_size) {
    const float* history     = (const float*)d_in[0];
    const float* color_rgb   = (const float*)d_in[1];
    const float* offset      = (const float*)d_in[2];
    const float* persistence = (const float*)d_in[3];
    const float* diffusion01 = (const float*)d_in[4];
    const float* dt_seconds  = (const float*)d_in[5];
    const float* amount01    = (const float*)d_in[6];
    const float* spread01    = (const float*)d_in[7];
    float* out = (float*)d_out;

    int nrows = in_sizes[0] / ROW_F;              // 65536
    int grid  = nrows / RPB;                      // 8192 (divides exactly)

    prep_kernel<<<1, RADIAL>>>(offset, persistence, diffusion01, dt_seconds,
                               amount01, spread01);
    beat_pulse_tma<<<grid, NT>>>(history, color_rgb, out);
}